// round 14
// baseline (speedup 1.0000x reference)
#include <cuda_runtime.h>
#include <cuda_bf16.h>
#include <math.h>

#define BATCH 64
#define TKLEN 400
#define HID   512
#define H2    1024
#define VOCAB 50000
#define VEXT  50100

__host__ __device__ constexpr int OFF_H()    { return BATCH * VEXT; }
__host__ __device__ constexpr int OFF_C()    { return OFF_H()  + BATCH * HID; }
__host__ __device__ constexpr int OFF_CT()   { return OFF_C()  + BATCH * HID; }
__host__ __device__ constexpr int OFF_ATTN() { return OFF_CT() + BATCH * H2; }
__host__ __device__ constexpr int OFF_PG()   { return OFF_ATTN() + BATCH * TKLEN; }
__host__ __device__ constexpr int OFF_COV()  { return OFF_PG() + BATCH; }
__host__ __device__ constexpr int OUT_FULL() { return OFF_COV() + BATCH * TKLEN; }

// scratch (device globals: no allocations allowed)
__device__ float g_xcatT[1152 * 64];
__device__ float g_actT [640  * 64];
__device__ float g_x    [64 * 128];
__device__ float g_gates[64 * 2048];
__device__ float g_h    [64 * 512];
__device__ float g_c    [64 * 512];
__device__ float g_sthatT[1024 * 64];
__device__ float g_decfea[64 * 1024];
__device__ float g_scores [64 * 400];
__device__ float g_scores2[64 * 400];
__device__ float g_attn   [64 * 400];
__device__ float g_astruct[64 * 400];
__device__ float g_cstruct[64 * 1024];
__device__ float g_o1actT[1536 * 64];
__device__ float g_pgen[64];
__device__ __nv_bfloat16 g_out1bf[64 * 512];
__device__ __nv_bfloat16 g_wrbf[1024 * 512];
__device__ float g_logits[(size_t)64 * 50000];

__device__ __forceinline__ float tanhax(float x) {
    float y; asm("tanh.approx.f32 %0, %1;" : "=f"(y) : "f"(x)); return y;
}
__device__ __forceinline__ float sigm(float x) { return 1.f / (1.f + __expf(-x)); }

__device__ __forceinline__ void st8bf(__nv_bfloat16* p, float4 x, float4 y) {
    __nv_bfloat162* q = (__nv_bfloat162*)p;
    q[0] = __float22bfloat162_rn(make_float2(x.x, x.y));
    q[1] = __float22bfloat162_rn(make_float2(x.z, x.w));
    q[2] = __float22bfloat162_rn(make_float2(y.x, y.y));
    q[3] = __float22bfloat162_rn(make_float2(y.z, y.w));
}

// ---- convert WrW to bf16 (524288 elems, 8 per thread) ----
__global__ void k_cvt(const float* __restrict__ wr) {
    int i = blockIdx.x * 256 + threadIdx.x;
    const float* p = wr + (size_t)i * 8;
    st8bf(&g_wrbf[(size_t)i * 8], *(const float4*)p, *(const float4*)(p + 4));
}

// ---- prep: transposed activations for skinny GEMMs ----
__global__ void k_prep(const int* __restrict__ y, const float* __restrict__ c_t_1,
                       const float* __restrict__ embW, const float* __restrict__ s_h) {
    int i = blockIdx.x * 256 + threadIdx.x;
    const int N1 = 1152 * 64, N2 = N1 + 512 * 64;
    if (i < N1) {
        int k = i >> 6, b = i & 63;
        g_xcatT[k * 64 + b] = (k < 1024) ? c_t_1[b * 1024 + k]
                                         : embW[(size_t)y[b] * 128 + (k - 1024)];
    } else if (i < N2) {
        int j = i - N1; int k = j >> 6, b = j & 63;
        g_actT[(128 + k) * 64 + b] = s_h[b * 512 + k];
    }
}

__device__ __forceinline__ float dot64(const float* __restrict__ W,
                                       const float* __restrict__ A, int K, int b) {
    float a0 = 0.f, a1 = 0.f, a2 = 0.f, a3 = 0.f;
    #pragma unroll 4
    for (int k = 0; k < K; k += 4) {
        a0 = fmaf(W[k],     A[(k)     * 64 + b], a0);
        a1 = fmaf(W[k + 1], A[(k + 1) * 64 + b], a1);
        a2 = fmaf(W[k + 2], A[(k + 2) * 64 + b], a2);
        a3 = fmaf(W[k + 3], A[(k + 3) * 64 + b], a3);
    }
    return (a0 + a1) + (a2 + a3);
}

__global__ void k_xc(const float* __restrict__ xcW, const float* __restrict__ xcb) {
    int b = threadIdx.x, j = blockIdx.x * 4 + threadIdx.y;
    float acc = xcb[j] + dot64(xcW + (size_t)j * 1152, g_xcatT, 1152, b);
    g_actT[j * 64 + b] = acc;
    g_x[b * 128 + j] = acc;
}

__global__ void k_gates(const float* __restrict__ Wih, const float* __restrict__ Whh,
                        const float* __restrict__ bih, const float* __restrict__ bhh) {
    int b = threadIdx.x, j = blockIdx.x * 4 + threadIdx.y;
    float acc = bih[j] + bhh[j];
    acc += dot64(Wih + (size_t)j * 128, g_actT, 128, b);
    acc += dot64(Whh + (size_t)j * 512, g_actT + 128 * 64, 512, b);
    g_gates[b * 2048 + j] = acc;
}

__global__ void k_cell(const float* __restrict__ s_c, float* __restrict__ out, int aux) {
    int i = blockIdx.x * 256 + threadIdx.x;
    int b = i >> 9, u = i & 511;
    const float* gr = g_gates + b * 2048;
    float cn = sigm(gr[512 + u]) * s_c[b * 512 + u] + sigm(gr[u]) * tanhax(gr[1024 + u]);
    float hn = sigm(gr[1536 + u]) * tanhax(cn);
    g_h[b * 512 + u] = hn;  g_c[b * 512 + u] = cn;
    g_sthatT[u * 64 + b] = hn;  g_sthatT[(512 + u) * 64 + b] = cn;
    g_o1actT[u * 64 + b] = hn;
    if (aux) { out[OFF_H() + i] = hn; out[OFF_C() + i] = cn; }
}

__global__ void k_decfea(const float* __restrict__ WsW, const float* __restrict__ Wsb) {
    int b = threadIdx.x, n = blockIdx.x * 4 + threadIdx.y;
    g_decfea[b * 1024 + n] = Wsb[n] + dot64(WsW + (size_t)n * 1024, g_sthatT, 1024, b);
}

// ---- mma helpers ----
__device__ __forceinline__ void mma_bf16(float* c, unsigned a0, unsigned a1, unsigned a2,
                                         unsigned a3, unsigned b0, unsigned b1) {
    asm volatile(
        "mma.sync.aligned.m16n8k16.row.col.f32.bf16.bf16.f32 "
        "{%0,%1,%2,%3}, {%4,%5,%6,%7}, {%8,%9}, {%0,%1,%2,%3};\n"
        : "+f"(c[0]), "+f"(c[1]), "+f"(c[2]), "+f"(c[3])
        : "r"(a0), "r"(a1), "r"(a2), "r"(a3), "r"(b0), "r"(b1));
}
__device__ __forceinline__ void ldmA(unsigned& a0, unsigned& a1, unsigned& a2, unsigned& a3,
                                     unsigned addr) {
    asm volatile("ldmatrix.sync.aligned.m8n8.x4.shared.b16 {%0,%1,%2,%3}, [%4];"
                 : "=r"(a0), "=r"(a1), "=r"(a2), "=r"(a3) : "r"(addr));
}
__device__ __forceinline__ void ldmB(unsigned& b0, unsigned& b1, unsigned addr) {
    asm volatile("ldmatrix.sync.aligned.m8n8.x2.shared.b16 {%0,%1}, [%2];"
                 : "=r"(b0), "=r"(b1) : "r"(addr));
}

// ---- scores2: A-resident smem, n-chunked, ldmatrix + HMMA, fused epilogue ----
#define S2_A_BYTES (128 * 520 * 2)          // 133120
#define S2_B_BYTES (2 * 128 * 24 * 2)       // 12288
#define S2_SMEM    (S2_A_BYTES + S2_B_BYTES + 128 * 4)

__global__ __launch_bounds__(512) void k_scores2(const float* __restrict__ ri,
                                                 const float* __restrict__ vW) {
    extern __shared__ char smraw[];
    __nv_bfloat16* As = (__nv_bfloat16*)smraw;                     // [128][520]
    __nv_bfloat16* Bs = (__nv_bfloat16*)(smraw + S2_A_BYTES);      // [2][128][24]
    float* s_sc = (float*)(smraw + S2_A_BYTES + S2_B_BYTES);       // [128]
    const int tid = threadIdx.x;
    const int m0 = blockIdx.x * 128;

    // load A tile 128x512 fp32 -> bf16 resident
    #pragma unroll
    for (int it = 0; it < 16; it++) {
        int idx = (tid + it * 512) * 8;              // element base
        int row = idx >> 9, col = idx & 511;
        const float* p = ri + (size_t)(m0 + row) * 512 + col;
        st8bf(&As[row * 520 + col], *(const float4*)p, *(const float4*)(p + 4));
    }
    if (tid < 128) s_sc[tid] = 0.f;
    __syncthreads();

    const int lane = tid & 31, wid = tid >> 5;
    const int wm = wid & 3, wn = wid >> 2;           // wm: 32-row slice, wn: 32-col slice
    const int g = lane >> 2, tg = lane & 3;

    // ldmatrix lane addressing
    unsigned As_u = (unsigned)__cvta_generic_to_shared(As);
    unsigned Bs_u = (unsigned)__cvta_generic_to_shared(Bs);
    int rowA = wm * 32 + (lane & 7) + ((lane >> 3) & 1) * 8;
    int colA = ((lane >> 4) & 1) * 8;
    unsigned aAddr0 = As_u + (rowA * 520 + colA) * 2;
    unsigned aAddr1 = aAddr0 + 16 * 520 * 2;
    unsigned bAddrBase[4];
    {
        int rB = (lane & 7), tB = (lane >> 3) & 1;
        #pragma unroll
        for (int nt = 0; nt < 4; nt++)
            bAddrBase[nt] = Bs_u + ((wn * 32 + nt * 8 + rB) * 24 + tB * 8) * 2;
    }

    const int rL = tid >> 1, cL = (tid & 1) * 8;     // B global loader mapping (tid<256)
    float preg[2][2] = {{0.f, 0.f}, {0.f, 0.f}};

    for (int nc = 0; nc < 8; nc++) {
        const int n0 = nc * 128;
        const __nv_bfloat16* gB = g_wrbf + (size_t)(n0 + rL) * 512 + cL;
        float acc[2][4][4];
        #pragma unroll
        for (int a = 0; a < 2; a++)
            #pragma unroll
            for (int b = 0; b < 4; b++)
                #pragma unroll
                for (int c = 0; c < 4; c++) acc[a][b][c] = 0.f;

        __syncthreads();                              // prior chunk reads done
        if (tid < 256) *(uint4*)&Bs[rL * 24 + cL] = *(const uint4*)gB;
        __syncthreads();

        int buf = 0;
        uint4 nxt;
        for (int kk = 0; kk < 32; kk++) {
            if (kk < 31 && tid < 256) nxt = *(const uint4*)(gB + (kk + 1) * 16);
            unsigned a0[4], a1[4];
            ldmA(a0[0], a0[1], a0[2], a0[3], aAddr0 + kk * 32);
            ldmA(a1[0], a1[1], a1[2], a1[3], aAddr1 + kk * 32);
            unsigned bofs = buf * (128 * 24 * 2);
            #pragma unroll
            for (int nt = 0; nt < 4; nt++) {
                unsigned b0, b1;
                ldmB(b0, b1, bAddrBase[nt] + bofs);
                mma_bf16(acc[0][nt], a0[0], a0[1], a0[2], a0[3], b0, b1);
                mma_bf16(acc[1][nt], a1[0], a1[1], a1[2], a1[3], b0, b1);
            }
            if (kk < 31) {
                if (tid < 256) *(uint4*)&Bs[(buf ^ 1) * (128 * 24) + rL * 24 + cL] = nxt;
                __syncthreads();
                buf ^= 1;
            }
        }
        // fused tanh + v-dot epilogue for this n-chunk
        #pragma unroll
        for (int mt = 0; mt < 2; mt++)
            #pragma unroll
            for (int half = 0; half < 2; half++) {
                int mg = m0 + wm * 32 + mt * 16 + g + half * 8;
                const float* df = g_decfea + (mg / TKLEN) * 1024;
                float p = 0.f;
                #pragma unroll
                for (int nt = 0; nt < 4; nt++) {
                    int nn = n0 + wn * 32 + nt * 8 + 2 * tg;
                    p += vW[nn]     * tanhax(acc[mt][nt][half * 2]     + df[nn]);
                    p += vW[nn + 1] * tanhax(acc[mt][nt][half * 2 + 1] + df[nn + 1]);
                }
                preg[mt][half] += p;
            }
    }
    #pragma unroll
    for (int mt = 0; mt < 2; mt++)
        #pragma unroll
        for (int half = 0; half < 2; half++) {
            float p = preg[mt][half];
            p += __shfl_xor_sync(0xffffffffu, p, 1);
            p += __shfl_xor_sync(0xffffffffu, p, 2);
            if (tg == 0) atomicAdd(&s_sc[wm * 32 + mt * 16 + g + half * 8], p);
        }
    __syncthreads();
    if (tid < 128) g_scores2[m0 + tid] = s_sc[tid];
}

// ---- scores: v . tanh(encFeat + dec_fea + cov*Wc), warp per (b,t) ----
__global__ void k_scores(const float* __restrict__ encFeat, const float* __restrict__ vW,
                         const float* __restrict__ WcW, const float* __restrict__ coverage) {
    int w = blockIdx.x * 8 + (threadIdx.x >> 5);
    int lane = threadIdx.x & 31, b = w / TKLEN;
    const float4* ef = (const float4*)(encFeat + (size_t)w * 1024);
    const float4* df = (const float4*)(g_decfea + b * 1024);
    const float4* v4 = (const float4*)vW;
    const float4* w4 = (const float4*)WcW;
    float cov = coverage[w], acc = 0.f;
    #pragma unroll
    for (int i = 0; i < 8; i++) {
        int id = lane + i * 32;
        float4 e = ef[id], d = df[id], vv = v4[id], wc = w4[id];
        acc += vv.x * tanhax(e.x + d.x + cov * wc.x);
        acc += vv.y * tanhax(e.y + d.y + cov * wc.y);
        acc += vv.z * tanhax(e.z + d.z + cov * wc.z);
        acc += vv.w * tanhax(e.w + d.w + cov * wc.w);
    }
    for (int o = 16; o > 0; o >>= 1) acc += __shfl_xor_sync(0xffffffffu, acc, o);
    if (lane == 0) g_scores[w] = acc;
}

// ---- both t-softmaxes ----
__global__ void k_softmax_t(const float* __restrict__ mask, const float* __restrict__ coverage,
                            float* __restrict__ out, int aux) {
    int b = blockIdx.x, t = threadIdx.x;
    __shared__ float sm[512];
    float s = (t < TKLEN) ? g_scores[b * TKLEN + t] : -1e30f;
    sm[t] = s; __syncthreads();
    for (int st = 256; st > 0; st >>= 1) { if (t < st) sm[t] = fmaxf(sm[t], sm[t + st]); __syncthreads(); }
    float mx = sm[0]; __syncthreads();
    float e = (t < TKLEN) ? __expf(s - mx) : 0.f;
    sm[t] = e; __syncthreads();
    for (int st = 256; st > 0; st >>= 1) { if (t < st) sm[t] += sm[t + st]; __syncthreads(); }
    float S = sm[0]; __syncthreads();
    float a = (t < TKLEN) ? (e / S) * mask[b * TKLEN + t] : 0.f;
    sm[t] = a; __syncthreads();
    for (int st = 256; st > 0; st >>= 1) { if (t < st) sm[t] += sm[t + st]; __syncthreads(); }
    float Sm = sm[0]; __syncthreads();
    if (t < TKLEN) {
        float attn = a / Sm;
        g_attn[b * TKLEN + t] = attn;
        if (aux) {
            out[OFF_ATTN() + b * TKLEN + t] = attn;
            out[OFF_COV()  + b * TKLEN + t] = coverage[b * TKLEN + t] + attn;
        }
    }
    __syncthreads();
    float s2 = (t < TKLEN) ? g_scores2[b * TKLEN + t] : -1e30f;
    sm[t] = s2; __syncthreads();
    for (int st = 256; st > 0; st >>= 1) { if (t < st) sm[t] = fmaxf(sm[t], sm[t + st]); __syncthreads(); }
    float mx2 = sm[0]; __syncthreads();
    float e2 = (t < TKLEN) ? __expf(s2 - mx2) : 0.f;
    sm[t] = e2; __syncthreads();
    for (int st = 256; st > 0; st >>= 1) { if (t < st) sm[t] += sm[t + st]; __syncthreads(); }
    float S2 = sm[0];
    if (t < TKLEN) g_astruct[b * TKLEN + t] = (e2 / S2) * mask[b * TKLEN + t];
}

// ---- c_t & c_struct in one pass ----
__global__ void k_ctx(const float* __restrict__ encOut, float* __restrict__ out, int aux) {
    int b = blockIdx.y, n = blockIdx.x * 256 + threadIdx.x;
    __shared__ float sa[400], sb2[400];
    for (int t = threadIdx.x; t < 400; t += 256) {
        sa[t]  = g_attn[b * TKLEN + t];
        sb2[t] = g_astruct[b * TKLEN + t];
    }
    __syncthreads();
    const float* E = encOut + (size_t)b * TKLEN * 1024 + n;
    float a1 = 0.f, a2 = 0.f;
    #pragma unroll 4
    for (int t = 0; t < 400; t++) {
        float e = E[(size_t)t * 1024];
        a1 = fmaf(sa[t], e, a1);
        a2 = fmaf(sb2[t], e, a2);
    }
    g_cstruct[b * 1024 + n] = a2;
    g_o1actT[(512 + n) * 64 + b] = a2;
    if (aux) out[OFF_CT() + b * 1024 + n] = a1;
}

__global__ void k_pgen(const float* __restrict__ pgW, const float* __restrict__ pgb,
                       float* __restrict__ out, int aux) {
    int b = blockIdx.x * 8 + (threadIdx.x >> 5), lane = threadIdx.x & 31;
    float acc = 0.f;
    for (int k = lane; k < 2176; k += 32) {
        float xv;
        if (k < 1024)      xv = g_cstruct[b * 1024 + k];
        else if (k < 1536) xv = g_h[b * 512 + k - 1024];
        else if (k < 2048) xv = g_c[b * 512 + k - 1536];
        else               xv = g_x[b * 128 + k - 2048];
        acc = fmaf(pgW[k], xv, acc);
    }
    for (int o = 16; o > 0; o >>= 1) acc += __shfl_xor_sync(0xffffffffu, acc, o);
    if (lane == 0) {
        float p = sigm(acc + pgb[0]);
        g_pgen[b] = p;
        if (aux) out[OFF_PG() + b] = p;
    }
}

__global__ void k_out1(const float* __restrict__ o1W, const float* __restrict__ o1b) {
    int b = threadIdx.x, o = blockIdx.x * 4 + threadIdx.y;
    float acc = o1b[o] + dot64(o1W + (size_t)o * 1536, g_o1actT, 1536, b);
    g_out1bf[b * 512 + o] = __float2bfloat16(acc);
}

// ---- logits (64 x 50000) bf16 MMA; tile 64m x 128n, K=512 ----
__global__ __launch_bounds__(256) void k_logits(const float* __restrict__ o2W,
                                                const float* __restrict__ o2b) {
    __shared__ __nv_bfloat16 As[2][64][24];
    __shared__ __nv_bfloat16 Bs[2][128][24];
    const int tid = threadIdx.x, n0 = blockIdx.x * 128;
    const int rA = tid >> 2, cA = (tid & 3) * 4;
    const __nv_bfloat16* aG = g_out1bf + rA * 512 + cA;
    const int rB = tid >> 1, cbB = (tid & 1) * 8, ngB = n0 + rB;
    const bool bok = (ngB < VOCAB);
    const float* bG = o2W + (size_t)ngB * 512 + cbB;

    __nv_bfloat162 pa0 = *(const __nv_bfloat162*)aG;
    __nv_bfloat162 pa1 = *(const __nv_bfloat162*)(aG + 2);
    float4 fb0 = make_float4(0, 0, 0, 0), fb1 = fb0;
    if (bok) { fb0 = *(const float4*)bG; fb1 = *(const float4*)(bG + 4); }
    *(__nv_bfloat162*)&As[0][rA][cA]     = pa0;
    *(__nv_bfloat162*)&As[0][rA][cA + 2] = pa1;
    st8bf(&Bs[0][rB][cbB], fb0, fb1);
    __syncthreads();

    const int lane = tid & 31, wid = tid >> 5;
    const int wm = wid & 1, wn = wid >> 1, g = lane >> 2, tg = lane & 3;
    float acc[2][4][4] = {};

    int buf = 0;
    for (int ks = 0; ks < 32; ks++) {
        if (ks < 31) {
            const __nv_bfloat16* ap = aG + (ks + 1) * 16;
            pa0 = *(const __nv_bfloat162*)ap; pa1 = *(const __nv_bfloat162*)(ap + 2);
            if (bok) {
                const float* bp = bG + (ks + 1) * 16;
                fb0 = *(const float4*)bp; fb1 = *(const float4*)(bp + 4);
            }
        }
        unsigned afr[2][4];
        #pragma unroll
        for (int mt = 0; mt < 2; mt++) {
            int rb = wm * 32 + mt * 16;
            afr[mt][0] = *(const unsigned*)&As[buf][rb + g][2 * tg];
            afr[mt][1] = *(const unsigned*)&As[buf][rb + g + 8][2 * tg];
            afr[mt][2] = *(const unsigned*)&As[buf][rb + g][2 * tg + 8];
            afr[mt][3] = *(const unsigned*)&As[buf][rb + g + 8][2 * tg + 8];
        }
        #pragma unroll
        for (int nt = 0; nt < 4; nt++) {
            int nr = wn * 32 + nt * 8 + g;
            unsigned b0 = *(const unsigned*)&Bs[buf][nr][2 * tg];
            unsigned b1 = *(const unsigned*)&Bs[buf][nr][2 * tg + 8];
            mma_bf16(acc[0][nt], afr[0][0], afr[0][1], afr[0][2], afr[0][3], b0, b1);
            mma_bf16(acc[1][nt], afr[1][0], afr[1][1], afr[1][2], afr[1][3], b0, b1);
        }
        if (ks < 31) {
            *(__nv_bfloat162*)&As[buf ^ 1][rA][cA]     = pa0;
            *(__nv_bfloat162*)&As[buf ^ 1][rA][cA + 2] = pa1;
            st8bf(&Bs[buf ^ 1][rB][cbB], fb0, fb1);
            __syncthreads();
            buf ^= 1;
        }
    }
    #pragma unroll
    for (int mt = 0; mt < 2; mt++)
        #pragma unroll
        for (int nt = 0; nt < 4; nt++) {
            int nn = n0 + wn * 32 + nt * 8 + 2 * tg;
            if (nn < VOCAB) {
                int mg = wm * 32 + mt * 16 + g;
                float bb0 = o2b[nn], bb1 = o2b[nn + 1];
                g_logits[(size_t)mg * VOCAB + nn]           = acc[mt][nt][0] + bb0;
                g_logits[(size_t)mg * VOCAB + nn + 1]       = acc[mt][nt][1] + bb1;
                g_logits[(size_t)(mg + 8) * VOCAB + nn]     = acc[mt][nt][2] + bb0;
                g_logits[(size_t)(mg + 8) * VOCAB + nn + 1] = acc[mt][nt][3] + bb1;
            }
        }
}

// ---- vocab softmax * p_gen + zeroed OOV ----
__global__ void k_vsoftmax(float* __restrict__ out) {
    int b = blockIdx.x, t = threadIdx.x;
    __shared__ float sm[1024];
    const float* L = g_logits + (size_t)b * VOCAB;
    float mx = -1e30f;
    for (int n = t; n < VOCAB; n += 1024) mx = fmaxf(mx, L[n]);
    sm[t] = mx; __syncthreads();
    for (int s = 512; s > 0; s >>= 1) { if (t < s) sm[t] = fmaxf(sm[t], sm[t + s]); __syncthreads(); }
    mx = sm[0]; __syncthreads();
    float sum = 0.f;
    for (int n = t; n < VOCAB; n += 1024) sum += __expf(L[n] - mx);
    sm[t] = sum; __syncthreads();
    for (int s = 512; s > 0; s >>= 1) { if (t < s) sm[t] += sm[t + s]; __syncthreads(); }
    float scale = g_pgen[b] / sm[0];
    float* O = out + (size_t)b * VEXT;
    for (int n = t; n < VEXT; n += 1024)
        O[n] = (n < VOCAB) ? scale * __expf(L[n] - mx) : 0.f;
}

__global__ void k_scatter(const int* __restrict__ ebev, float* __restrict__ out) {
    int i = blockIdx.x * 256 + threadIdx.x;
    if (i >= BATCH * TKLEN) return;
    int b = i / TKLEN;
    atomicAdd(&out[(size_t)b * VEXT + ebev[i]], (1.f - g_pgen[b]) * g_attn[i]);
}

extern "C" void kernel_launch(void* const* d_in, const int* in_sizes, int n_in,
                              void* d_out, int out_size) {
    const int*   y        = (const int*)  d_in[0];
    const float* s_h      = (const float*)d_in[1];
    const float* s_c      = (const float*)d_in[2];
    const float* encOut   = (const float*)d_in[3];
    const float* encFeat  = (const float*)d_in[4];
    const float* mask     = (const float*)d_in[5];
    const float* c_t_1    = (const float*)d_in[6];
    const int*   ebev     = (const int*)  d_in[8];
    const float* coverage = (const float*)d_in[9];
    const int q = (n_in > 10 && in_sizes[10] <= 4) ? 11 : 10;
    const float* ri   = (const float*)d_in[q + 0];
    const float* embW = (const float*)d_in[q + 1];
    const float* WsW  = (const float*)d_in[q + 2];
    const float* Wsb  = (const float*)d_in[q + 3];
    const float* vW   = (const float*)d_in[q + 4];
    const float* WcW  = (const float*)d_in[q + 5];
    const float* WrW  = (const float*)d_in[q + 6];
    const float* xcW  = (const float*)d_in[q + 7];
    const float* xcb  = (const float*)d_in[q + 8];
    const float* Wih  = (const float*)d_in[q + 9];
    const float* Whh  = (const float*)d_in[q + 10];
    const float* bih  = (const float*)d_in[q + 11];
    const float* bhh  = (const float*)d_in[q + 12];
    const float* pgW  = (const float*)d_in[q + 13];
    const float* pgb  = (const float*)d_in[q + 14];
    const float* o1W  = (const float*)d_in[q + 15];
    const float* o1b  = (const float*)d_in[q + 16];
    const float* o2W  = (const float*)d_in[q + 17];
    const float* o2b  = (const float*)d_in[q + 18];
    float* out = (float*)d_out;
    const int aux = (out_size >= OUT_FULL()) ? 1 : 0;

    static int smem_set = 0;
    if (!smem_set) {
        cudaFuncSetAttribute(k_scores2, cudaFuncAttributeMaxDynamicSharedMemorySize, S2_SMEM);
        smem_set = 1;
    }

    dim3 b64x4(64, 4);
    k_cvt<<<256, 256>>>(WrW);
    k_prep<<<416, 256>>>(y, c_t_1, embW, s_h);
    k_xc<<<32, b64x4>>>(xcW, xcb);
    k_gates<<<512, b64x4>>>(Wih, Whh, bih, bhh);
    k_cell<<<128, 256>>>(s_c, out, aux);
    k_decfea<<<256, b64x4>>>(WsW, Wsb);
    k_scores2<<<200, 512, S2_SMEM>>>(ri, vW);
    k_scores<<<3200, 256>>>(encFeat, vW, WcW, coverage);
    k_softmax_t<<<64, 512>>>(mask, coverage, out, aux);
    k_ctx<<<dim3(4, 64), 256>>>(encOut, out, aux);
    k_pgen<<<8, 256>>>(pgW, pgb, out, aux);
    k_out1<<<128, b64x4>>>(o1W, o1b);
    k_logits<<<391, 256>>>(o2W, o2b);
    k_vsoftmax<<<64, 1024>>>(out);
    k_scatter<<<100, 256>>>(ebev, out);
}

// round 15
// speedup vs baseline: 1.4265x; 1.4265x over previous
#include <cuda_runtime.h>
#include <cuda_bf16.h>
#include <math.h>

#define BATCH 64
#define TKLEN 400
#define HID   512
#define H2    1024
#define VOCAB 50000
#define VEXT  50100

__host__ __device__ constexpr int OFF_H()    { return BATCH * VEXT; }
__host__ __device__ constexpr int OFF_C()    { return OFF_H()  + BATCH * HID; }
__host__ __device__ constexpr int OFF_CT()   { return OFF_C()  + BATCH * HID; }
__host__ __device__ constexpr int OFF_ATTN() { return OFF_CT() + BATCH * H2; }
__host__ __device__ constexpr int OFF_PG()   { return OFF_ATTN() + BATCH * TKLEN; }
__host__ __device__ constexpr int OFF_COV()  { return OFF_PG() + BATCH; }
__host__ __device__ constexpr int OUT_FULL() { return OFF_COV() + BATCH * TKLEN; }

// scratch (device globals: no allocations allowed) — all b-major
__device__ float g_xcat2 [64 * 1152];   // [c_t_1 ; y_emb]
__device__ float g_act2  [64 * 640];    // [x(128) ; h0(512)]
__device__ float g_gates [64 * 2048];
__device__ float g_c     [64 * 512];
__device__ float g_sthat2[64 * 1024];   // [h ; c]
__device__ float g_o1act2[64 * 1536];   // [h(512) ; c_struct(1024)]
__device__ float g_decfea[64 * 1024];
__device__ float g_scores [64 * 400];
__device__ float g_scores2[64 * 400];
__device__ float g_attn   [64 * 400];
__device__ float g_astruct[64 * 400];
__device__ float g_pgen[64];
__device__ __nv_bfloat16 g_out1bf[64 * 512];
__device__ __nv_bfloat16 g_wrbf[1024 * 512];
__device__ float g_logits[(size_t)64 * 50000];

__device__ __forceinline__ float tanhax(float x) {
    float y; asm("tanh.approx.f32 %0, %1;" : "=f"(y) : "f"(x)); return y;
}
__device__ __forceinline__ float sigm(float x) { return 1.f / (1.f + __expf(-x)); }

__device__ __forceinline__ void st8bf(__nv_bfloat16* p, float4 x, float4 y) {
    __nv_bfloat162* q = (__nv_bfloat162*)p;
    q[0] = __float22bfloat162_rn(make_float2(x.x, x.y));
    q[1] = __float22bfloat162_rn(make_float2(x.z, x.w));
    q[2] = __float22bfloat162_rn(make_float2(y.x, y.y));
    q[3] = __float22bfloat162_rn(make_float2(y.z, y.w));
}

// ---- convert WrW to bf16 ----
__global__ void k_cvt(const float* __restrict__ wr) {
    int i = blockIdx.x * 256 + threadIdx.x;
    const float* p = wr + (size_t)i * 8;
    st8bf(&g_wrbf[(size_t)i * 8], *(const float4*)p, *(const float4*)(p + 4));
}

// ---- prep: b-major activation concats ----
__global__ void k_prep(const int* __restrict__ y, const float* __restrict__ c_t_1,
                       const float* __restrict__ embW, const float* __restrict__ s_h) {
    int i = blockIdx.x * 256 + threadIdx.x;
    const int N1 = 64 * 1152;
    if (i < N1) {
        int b = i / 1152, k = i - b * 1152;
        g_xcat2[i] = (k < 1024) ? c_t_1[b * 1024 + k]
                                : embW[(size_t)y[b] * 128 + (k - 1024)];
    } else if (i < N1 + 64 * 512) {
        int j = i - N1; int b = j >> 9, k = j & 511;
        g_act2[b * 640 + 128 + k] = s_h[b * 512 + k];
    }
}

// ---- warp-split-K skinny GEMM core: 4 j x 8 b per warp ----
__device__ __forceinline__ void skinny_acc(const float* __restrict__ W, int ldw,
                                           const float* __restrict__ A, int lda,
                                           int K, int j0, int b0, int lane, float* acc) {
    for (int k = lane; k < K; k += 32) {
        float wv0 = W[(size_t)(j0 + 0) * ldw + k];
        float wv1 = W[(size_t)(j0 + 1) * ldw + k];
        float wv2 = W[(size_t)(j0 + 2) * ldw + k];
        float wv3 = W[(size_t)(j0 + 3) * ldw + k];
        float av[8];
        #pragma unroll
        for (int bb = 0; bb < 8; bb++) av[bb] = A[(b0 + bb) * lda + k];
        #pragma unroll
        for (int bb = 0; bb < 8; bb++) {
            acc[0 * 8 + bb] = fmaf(wv0, av[bb], acc[0 * 8 + bb]);
            acc[1 * 8 + bb] = fmaf(wv1, av[bb], acc[1 * 8 + bb]);
            acc[2 * 8 + bb] = fmaf(wv2, av[bb], acc[2 * 8 + bb]);
            acc[3 * 8 + bb] = fmaf(wv3, av[bb], acc[3 * 8 + bb]);
        }
    }
}
__device__ __forceinline__ void skinny_red(float* acc) {
    #pragma unroll
    for (int i = 0; i < 32; i++) {
        float v = acc[i];
        v += __shfl_xor_sync(0xffffffffu, v, 16);
        v += __shfl_xor_sync(0xffffffffu, v, 8);
        v += __shfl_xor_sync(0xffffffffu, v, 4);
        v += __shfl_xor_sync(0xffffffffu, v, 2);
        v += __shfl_xor_sync(0xffffffffu, v, 1);
        acc[i] = v;
    }
}

// x = xc([c_t_1, y_emb]); J=128, K=1152 → grid 32
__global__ void k_xc(const float* __restrict__ xcW, const float* __restrict__ xcb) {
    int w = blockIdx.x * 8 + (threadIdx.x >> 5), lane = threadIdx.x & 31;
    int j0 = (w >> 3) * 4, b0 = (w & 7) * 8;
    float acc[32];
    #pragma unroll
    for (int i = 0; i < 32; i++) acc[i] = 0.f;
    skinny_acc(xcW, 1152, g_xcat2, 1152, 1152, j0, b0, lane, acc);
    skinny_red(acc);
    if (lane == 0) {
        #pragma unroll
        for (int jj = 0; jj < 4; jj++) {
            float bv = xcb[j0 + jj];
            #pragma unroll
            for (int bb = 0; bb < 8; bb++)
                g_act2[(b0 + bb) * 640 + j0 + jj] = bv + acc[jj * 8 + bb];
        }
    }
}

// gates; J=2048, K=128+512 → grid 512
__global__ void k_gates(const float* __restrict__ Wih, const float* __restrict__ Whh,
                        const float* __restrict__ bih, const float* __restrict__ bhh) {
    int w = blockIdx.x * 8 + (threadIdx.x >> 5), lane = threadIdx.x & 31;
    int j0 = (w >> 3) * 4, b0 = (w & 7) * 8;
    float acc[32];
    #pragma unroll
    for (int i = 0; i < 32; i++) acc[i] = 0.f;
    skinny_acc(Wih, 128, g_act2, 640, 128, j0, b0, lane, acc);
    skinny_acc(Whh, 512, g_act2 + 128, 640, 512, j0, b0, lane, acc);
    skinny_red(acc);
    if (lane == 0) {
        #pragma unroll
        for (int jj = 0; jj < 4; jj++) {
            float bv = bih[j0 + jj] + bhh[j0 + jj];
            #pragma unroll
            for (int bb = 0; bb < 8; bb++)
                g_gates[(b0 + bb) * 2048 + j0 + jj] = bv + acc[jj * 8 + bb];
        }
    }
}

__global__ void k_cell(const float* __restrict__ s_c, float* __restrict__ out, int aux) {
    int i = blockIdx.x * 256 + threadIdx.x;
    int b = i >> 9, u = i & 511;
    const float* gr = g_gates + b * 2048;
    float cn = sigm(gr[512 + u]) * s_c[b * 512 + u] + sigm(gr[u]) * tanhax(gr[1024 + u]);
    float hn = sigm(gr[1536 + u]) * tanhax(cn);
    g_c[b * 512 + u] = cn;
    g_sthat2[b * 1024 + u] = hn;  g_sthat2[b * 1024 + 512 + u] = cn;
    g_o1act2[b * 1536 + u] = hn;
    if (aux) { out[OFF_H() + i] = hn; out[OFF_C() + i] = cn; }
}

// dec_fea = Ws(s_t_hat); J=1024, K=1024 → grid 256
__global__ void k_decfea(const float* __restrict__ WsW, const float* __restrict__ Wsb) {
    int w = blockIdx.x * 8 + (threadIdx.x >> 5), lane = threadIdx.x & 31;
    int j0 = (w >> 3) * 4, b0 = (w & 7) * 8;
    float acc[32];
    #pragma unroll
    for (int i = 0; i < 32; i++) acc[i] = 0.f;
    skinny_acc(WsW, 1024, g_sthat2, 1024, 1024, j0, b0, lane, acc);
    skinny_red(acc);
    if (lane == 0) {
        #pragma unroll
        for (int jj = 0; jj < 4; jj++) {
            float bv = Wsb[j0 + jj];
            #pragma unroll
            for (int bb = 0; bb < 8; bb++)
                g_decfea[(b0 + bb) * 1024 + j0 + jj] = bv + acc[jj * 8 + bb];
        }
    }
}

// ---- mma helpers ----
__device__ __forceinline__ void mma_bf16(float* c, unsigned a0, unsigned a1, unsigned a2,
                                         unsigned a3, unsigned b0, unsigned b1) {
    asm volatile(
        "mma.sync.aligned.m16n8k16.row.col.f32.bf16.bf16.f32 "
        "{%0,%1,%2,%3}, {%4,%5,%6,%7}, {%8,%9}, {%0,%1,%2,%3};\n"
        : "+f"(c[0]), "+f"(c[1]), "+f"(c[2]), "+f"(c[3])
        : "r"(a0), "r"(a1), "r"(a2), "r"(a3), "r"(b0), "r"(b1));
}
__device__ __forceinline__ void ldmA(unsigned& a0, unsigned& a1, unsigned& a2, unsigned& a3,
                                     unsigned addr) {
    asm volatile("ldmatrix.sync.aligned.m8n8.x4.shared.b16 {%0,%1,%2,%3}, [%4];"
                 : "=r"(a0), "=r"(a1), "=r"(a2), "=r"(a3) : "r"(addr));
}
__device__ __forceinline__ void ldmB(unsigned& b0, unsigned& b1, unsigned addr) {
    asm volatile("ldmatrix.sync.aligned.m8n8.x2.shared.b16 {%0,%1}, [%2];"
                 : "=r"(b0), "=r"(b1) : "r"(addr));
}

// ---- scores2: A-resident smem, n-chunked, k-panel (64) B staging ----
#define S2_ABYT (128 * 520 * 2)         // 133120
#define S2_BROW 72
#define S2_BBUF (128 * S2_BROW)         // elems per buffer
#define S2_BBYT (2 * S2_BBUF * 2)       // 36864
#define S2_SMEM (S2_ABYT + S2_BBYT + 512)

__global__ __launch_bounds__(512) void k_scores2(const float* __restrict__ ri,
                                                 const float* __restrict__ vW) {
    extern __shared__ char smraw[];
    __nv_bfloat16* As = (__nv_bfloat16*)smraw;                 // [128][520]
    __nv_bfloat16* Bs = (__nv_bfloat16*)(smraw + S2_ABYT);     // [2][128][72]
    float* s_sc = (float*)(smraw + S2_ABYT + S2_BBYT);         // [128]
    const int tid = threadIdx.x;
    const int m0 = blockIdx.x * 128;

    #pragma unroll
    for (int it = 0; it < 16; it++) {
        int idx = (tid + it * 512) * 8;
        int row = idx >> 9, col = idx & 511;
        const float* p = ri + (size_t)(m0 + row) * 512 + col;
        st8bf(&As[row * 520 + col], *(const float4*)p, *(const float4*)(p + 4));
    }
    if (tid < 128) s_sc[tid] = 0.f;
    __syncthreads();

    const int lane = tid & 31, wid = tid >> 5;
    const int wm = wid & 3, wn = wid >> 2, g = lane >> 2, tg = lane & 3;

    unsigned As_u = (unsigned)__cvta_generic_to_shared(As);
    unsigned Bs_u = (unsigned)__cvta_generic_to_shared(Bs);
    int rowA = wm * 32 + (lane & 7) + ((lane >> 3) & 1) * 8;
    int colA = ((lane >> 4) & 1) * 8;
    unsigned aAddr0 = As_u + (rowA * 520 + colA) * 2;
    unsigned aAddr1 = aAddr0 + 16 * 520 * 2;
    unsigned bB[4];
    {
        int nR = lane & 7, tB = (lane >> 3) & 1;
        #pragma unroll
        for (int nt = 0; nt < 4; nt++)
            bB[nt] = Bs_u + ((wn * 32 + nt * 8 + nR) * S2_BROW + tB * 8) * 2;
    }
    // B panel loader: 2 uint4 per thread per panel
    const int r0 = tid >> 3, q0 = (tid & 7) * 8;
    const int r1 = (tid + 512) >> 3, q1 = ((tid + 512) & 7) * 8;

    float preg[2][2] = {{0.f, 0.f}, {0.f, 0.f}};
    int buf = 0;
    for (int nc = 0; nc < 8; nc++) {
        const int n0 = nc * 128;
        float acc[2][4][4];
        #pragma unroll
        for (int a = 0; a < 2; a++)
            #pragma unroll
            for (int b = 0; b < 4; b++)
                #pragma unroll
                for (int c = 0; c < 4; c++) acc[a][b][c] = 0.f;

        uint4 v0 = *(const uint4*)(g_wrbf + (size_t)(n0 + r0) * 512 + q0);
        uint4 v1 = *(const uint4*)(g_wrbf + (size_t)(n0 + r1) * 512 + q1);
        __syncthreads();   // all reads of Bs done
        *(uint4*)&Bs[buf * S2_BBUF + r0 * S2_BROW + q0] = v0;
        *(uint4*)&Bs[buf * S2_BBUF + r1 * S2_BROW + q1] = v1;
        __syncthreads();

        for (int kb = 0; kb < 8; kb++) {
            if (kb < 7) {
                v0 = *(const uint4*)(g_wrbf + (size_t)(n0 + r0) * 512 + (kb + 1) * 64 + q0);
                v1 = *(const uint4*)(g_wrbf + (size_t)(n0 + r1) * 512 + (kb + 1) * 64 + q1);
            }
            unsigned abyt = kb * 128;   // (kb*64 elems)*2
            unsigned bbuf = buf * (S2_BBUF * 2);
            #pragma unroll
            for (int kk = 0; kk < 4; kk++) {
                unsigned a0[4], a1[4];
                ldmA(a0[0], a0[1], a0[2], a0[3], aAddr0 + abyt + kk * 32);
                ldmA(a1[0], a1[1], a1[2], a1[3], aAddr1 + abyt + kk * 32);
                #pragma unroll
                for (int nt = 0; nt < 4; nt++) {
                    unsigned b0, b1;
                    ldmB(b0, b1, bB[nt] + bbuf + kk * 32);
                    mma_bf16(acc[0][nt], a0[0], a0[1], a0[2], a0[3], b0, b1);
                    mma_bf16(acc[1][nt], a1[0], a1[1], a1[2], a1[3], b0, b1);
                }
            }
            if (kb < 7) {
                *(uint4*)&Bs[(buf ^ 1) * S2_BBUF + r0 * S2_BROW + q0] = v0;
                *(uint4*)&Bs[(buf ^ 1) * S2_BBUF + r1 * S2_BROW + q1] = v1;
                __syncthreads();
                buf ^= 1;
            }
        }
        // fused tanh + v-dot epilogue
        #pragma unroll
        for (int mt = 0; mt < 2; mt++)
            #pragma unroll
            for (int half = 0; half < 2; half++) {
                int mg = m0 + wm * 32 + mt * 16 + g + half * 8;
                const float* df = g_decfea + (mg / TKLEN) * 1024;
                float p = 0.f;
                #pragma unroll
                for (int nt = 0; nt < 4; nt++) {
                    int nn = n0 + wn * 32 + nt * 8 + 2 * tg;
                    p += vW[nn]     * tanhax(acc[mt][nt][half * 2]     + df[nn]);
                    p += vW[nn + 1] * tanhax(acc[mt][nt][half * 2 + 1] + df[nn + 1]);
                }
                preg[mt][half] += p;
            }
    }
    #pragma unroll
    for (int mt = 0; mt < 2; mt++)
        #pragma unroll
        for (int half = 0; half < 2; half++) {
            float p = preg[mt][half];
            p += __shfl_xor_sync(0xffffffffu, p, 1);
            p += __shfl_xor_sync(0xffffffffu, p, 2);
            if (tg == 0) atomicAdd(&s_sc[wm * 32 + mt * 16 + g + half * 8], p);
        }
    __syncthreads();
    if (tid < 128) g_scores2[m0 + tid] = s_sc[tid];
}

// ---- scores: v . tanh(encFeat + dec_fea + cov*Wc), warp per (b,t) ----
__global__ void k_scores(const float* __restrict__ encFeat, const float* __restrict__ vW,
                         const float* __restrict__ WcW, const float* __restrict__ coverage) {
    int w = blockIdx.x * 8 + (threadIdx.x >> 5);
    int lane = threadIdx.x & 31, b = w / TKLEN;
    const float4* ef = (const float4*)(encFeat + (size_t)w * 1024);
    const float4* df = (const float4*)(g_decfea + b * 1024);
    const float4* v4 = (const float4*)vW;
    const float4* w4 = (const float4*)WcW;
    float cov = coverage[w], acc = 0.f;
    #pragma unroll
    for (int i = 0; i < 8; i++) {
        int id = lane + i * 32;
        float4 e = ef[id], d = df[id], vv = v4[id], wc = w4[id];
        acc += vv.x * tanhax(e.x + d.x + cov * wc.x);
        acc += vv.y * tanhax(e.y + d.y + cov * wc.y);
        acc += vv.z * tanhax(e.z + d.z + cov * wc.z);
        acc += vv.w * tanhax(e.w + d.w + cov * wc.w);
    }
    for (int o = 16; o > 0; o >>= 1) acc += __shfl_xor_sync(0xffffffffu, acc, o);
    if (lane == 0) g_scores[w] = acc;
}

// ---- both t-softmaxes ----
__global__ void k_softmax_t(const float* __restrict__ mask, const float* __restrict__ coverage,
                            float* __restrict__ out, int aux) {
    int b = blockIdx.x, t = threadIdx.x;
    __shared__ float sm[512];
    float s = (t < TKLEN) ? g_scores[b * TKLEN + t] : -1e30f;
    sm[t] = s; __syncthreads();
    for (int st = 256; st > 0; st >>= 1) { if (t < st) sm[t] = fmaxf(sm[t], sm[t + st]); __syncthreads(); }
    float mx = sm[0]; __syncthreads();
    float e = (t < TKLEN) ? __expf(s - mx) : 0.f;
    sm[t] = e; __syncthreads();
    for (int st = 256; st > 0; st >>= 1) { if (t < st) sm[t] += sm[t + st]; __syncthreads(); }
    float S = sm[0]; __syncthreads();
    float a = (t < TKLEN) ? (e / S) * mask[b * TKLEN + t] : 0.f;
    sm[t] = a; __syncthreads();
    for (int st = 256; st > 0; st >>= 1) { if (t < st) sm[t] += sm[t + st]; __syncthreads(); }
    float Sm = sm[0]; __syncthreads();
    if (t < TKLEN) {
        float attn = a / Sm;
        g_attn[b * TKLEN + t] = attn;
        if (aux) {
            out[OFF_ATTN() + b * TKLEN + t] = attn;
            out[OFF_COV()  + b * TKLEN + t] = coverage[b * TKLEN + t] + attn;
        }
    }
    __syncthreads();
    float s2 = (t < TKLEN) ? g_scores2[b * TKLEN + t] : -1e30f;
    sm[t] = s2; __syncthreads();
    for (int st = 256; st > 0; st >>= 1) { if (t < st) sm[t] = fmaxf(sm[t], sm[t + st]); __syncthreads(); }
    float mx2 = sm[0]; __syncthreads();
    float e2 = (t < TKLEN) ? __expf(s2 - mx2) : 0.f;
    sm[t] = e2; __syncthreads();
    for (int st = 256; st > 0; st >>= 1) { if (t < st) sm[t] += sm[t + st]; __syncthreads(); }
    float S2 = sm[0];
    if (t < TKLEN) g_astruct[b * TKLEN + t] = (e2 / S2) * mask[b * TKLEN + t];
}

// ---- c_t & c_struct in one pass ----
__global__ void k_ctx(const float* __restrict__ encOut, float* __restrict__ out, int aux) {
    int b = blockIdx.y, n = blockIdx.x * 256 + threadIdx.x;
    __shared__ float sa[400], sb2[400];
    for (int t = threadIdx.x; t < 400; t += 256) {
        sa[t]  = g_attn[b * TKLEN + t];
        sb2[t] = g_astruct[b * TKLEN + t];
    }
    __syncthreads();
    const float* E = encOut + (size_t)b * TKLEN * 1024 + n;
    float a1 = 0.f, a2 = 0.f;
    #pragma unroll 4
    for (int t = 0; t < 400; t++) {
        float e = E[(size_t)t * 1024];
        a1 = fmaf(sa[t], e, a1);
        a2 = fmaf(sb2[t], e, a2);
    }
    g_o1act2[b * 1536 + 512 + n] = a2;
    if (aux) out[OFF_CT() + b * 1024 + n] = a1;
}

__global__ void k_pgen(const float* __restrict__ pgW, const float* __restrict__ pgb,
                       float* __restrict__ out, int aux) {
    int b = blockIdx.x * 8 + (threadIdx.x >> 5), lane = threadIdx.x & 31;
    float acc = 0.f;
    for (int k = lane; k < 2176; k += 32) {
        float xv;
        if (k < 1024)      xv = g_o1act2[b * 1536 + 512 + k];          // c_struct
        else if (k < 1536) xv = g_o1act2[b * 1536 + (k - 1024)];       // h
        else if (k < 2048) xv = g_c[b * 512 + k - 1536];               // c
        else               xv = g_act2[b * 640 + (k - 2048)];          // x
        acc = fmaf(pgW[k], xv, acc);
    }
    for (int o = 16; o > 0; o >>= 1) acc += __shfl_xor_sync(0xffffffffu, acc, o);
    if (lane == 0) {
        float p = sigm(acc + pgb[0]);
        g_pgen[b] = p;
        if (aux) out[OFF_PG() + b] = p;
    }
}

// out1 = o1([h, c_struct]) -> bf16; J=512, K=1536 → grid 128
__global__ void k_out1(const float* __restrict__ o1W, const float* __restrict__ o1b) {
    int w = blockIdx.x * 8 + (threadIdx.x >> 5), lane = threadIdx.x & 31;
    int j0 = (w >> 3) * 4, b0 = (w & 7) * 8;
    float acc[32];
    #pragma unroll
    for (int i = 0; i < 32; i++) acc[i] = 0.f;
    skinny_acc(o1W, 1536, g_o1act2, 1536, 1536, j0, b0, lane, acc);
    skinny_red(acc);
    if (lane == 0) {
        #pragma unroll
        for (int jj = 0; jj < 4; jj++) {
            float bv = o1b[j0 + jj];
            #pragma unroll
            for (int bb = 0; bb < 8; bb++)
                g_out1bf[(b0 + bb) * 512 + j0 + jj] = __float2bfloat16(bv + acc[jj * 8 + bb]);
        }
    }
}

// ---- logits (64 x 50000) bf16 MMA; tile 64m x 128n, K=512 ----
__global__ __launch_bounds__(256) void k_logits(const float* __restrict__ o2W,
                                                const float* __restrict__ o2b) {
    __shared__ __nv_bfloat16 As[2][64][24];
    __shared__ __nv_bfloat16 Bs[2][128][24];
    const int tid = threadIdx.x, n0 = blockIdx.x * 128;
    const int rA = tid >> 2, cA = (tid & 3) * 4;
    const __nv_bfloat16* aG = g_out1bf + rA * 512 + cA;
    const int rB = tid >> 1, cbB = (tid & 1) * 8, ngB = n0 + rB;
    const bool bok = (ngB < VOCAB);
    const float* bG = o2W + (size_t)ngB * 512 + cbB;

    __nv_bfloat162 pa0 = *(const __nv_bfloat162*)aG;
    __nv_bfloat162 pa1 = *(const __nv_bfloat162*)(aG + 2);
    float4 fb0 = make_float4(0, 0, 0, 0), fb1 = fb0;
    if (bok) { fb0 = *(const float4*)bG; fb1 = *(const float4*)(bG + 4); }
    *(__nv_bfloat162*)&As[0][rA][cA]     = pa0;
    *(__nv_bfloat162*)&As[0][rA][cA + 2] = pa1;
    st8bf(&Bs[0][rB][cbB], fb0, fb1);
    __syncthreads();

    const int lane = tid & 31, wid = tid >> 5;
    const int wm = wid & 1, wn = wid >> 1, g = lane >> 2, tg = lane & 3;
    float acc[2][4][4] = {};

    int buf = 0;
    for (int ks = 0; ks < 32; ks++) {
        if (ks < 31) {
            const __nv_bfloat16* ap = aG + (ks + 1) * 16;
            pa0 = *(const __nv_bfloat162*)ap; pa1 = *(const __nv_bfloat162*)(ap + 2);
            if (bok) {
                const float* bp = bG + (ks + 1) * 16;
                fb0 = *(const float4*)bp; fb1 = *(const float4*)(bp + 4);
            }
        }
        unsigned afr[2][4];
        #pragma unroll
        for (int mt = 0; mt < 2; mt++) {
            int rb = wm * 32 + mt * 16;
            afr[mt][0] = *(const unsigned*)&As[buf][rb + g][2 * tg];
            afr[mt][1] = *(const unsigned*)&As[buf][rb + g + 8][2 * tg];
            afr[mt][2] = *(const unsigned*)&As[buf][rb + g][2 * tg + 8];
            afr[mt][3] = *(const unsigned*)&As[buf][rb + g + 8][2 * tg + 8];
        }
        #pragma unroll
        for (int nt = 0; nt < 4; nt++) {
            int nr = wn * 32 + nt * 8 + g;
            unsigned b0 = *(const unsigned*)&Bs[buf][nr][2 * tg];
            unsigned b1 = *(const unsigned*)&Bs[buf][nr][2 * tg + 8];
            mma_bf16(acc[0][nt], afr[0][0], afr[0][1], afr[0][2], afr[0][3], b0, b1);
            mma_bf16(acc[1][nt], afr[1][0], afr[1][1], afr[1][2], afr[1][3], b0, b1);
        }
        if (ks < 31) {
            *(__nv_bfloat162*)&As[buf ^ 1][rA][cA]     = pa0;
            *(__nv_bfloat162*)&As[buf ^ 1][rA][cA + 2] = pa1;
            st8bf(&Bs[buf ^ 1][rB][cbB], fb0, fb1);
            __syncthreads();
            buf ^= 1;
        }
    }
    #pragma unroll
    for (int mt = 0; mt < 2; mt++)
        #pragma unroll
        for (int nt = 0; nt < 4; nt++) {
            int nn = n0 + wn * 32 + nt * 8 + 2 * tg;
            if (nn < VOCAB) {
                int mg = wm * 32 + mt * 16 + g;
                float bb0 = o2b[nn], bb1 = o2b[nn + 1];
                g_logits[(size_t)mg * VOCAB + nn]           = acc[mt][nt][0] + bb0;
                g_logits[(size_t)mg * VOCAB + nn + 1]       = acc[mt][nt][1] + bb1;
                g_logits[(size_t)(mg + 8) * VOCAB + nn]     = acc[mt][nt][2] + bb0;
                g_logits[(size_t)(mg + 8) * VOCAB + nn + 1] = acc[mt][nt][3] + bb1;
            }
        }
}

// ---- vocab softmax * p_gen + zeroed OOV ----
__global__ void k_vsoftmax(float* __restrict__ out) {
    int b = blockIdx.x, t = threadIdx.x;
    __shared__ float sm[1024];
    const float* L = g_logits + (size_t)b * VOCAB;
    float mx = -1e30f;
    for (int n = t; n < VOCAB; n += 1024) mx = fmaxf(mx, L[n]);
    sm[t] = mx; __syncthreads();
    for (int s = 512; s > 0; s >>= 1) { if (t < s) sm[t] = fmaxf(sm[t], sm[t + s]); __syncthreads(); }
    mx = sm[0]; __syncthreads();
    float sum = 0.f;
    for (int n = t; n < VOCAB; n += 1024) sum += __expf(L[n] - mx);
    sm[t] = sum; __syncthreads();
    for (int s = 512; s > 0; s >>= 1) { if (t < s) sm[t] += sm[t + s]; __syncthreads(); }
    float scale = g_pgen[b] / sm[0];
    float* O = out + (size_t)b * VEXT;
    for (int n = t; n < VEXT; n += 1024)
        O[n] = (n < VOCAB) ? scale * __expf(L[n] - mx) : 0.f;
}

__global__ void k_scatter(const int* __restrict__ ebev, float* __restrict__ out) {
    int i = blockIdx.x * 256 + threadIdx.x;
    if (i >= BATCH * TKLEN) return;
    int b = i / TKLEN;
    atomicAdd(&out[(size_t)b * VEXT + ebev[i]], (1.f - g_pgen[b]) * g_attn[i]);
}

extern "C" void kernel_launch(void* const* d_in, const int* in_sizes, int n_in,
                              void* d_out, int out_size) {
    const int*   y        = (const int*)  d_in[0];
    const float* s_h      = (const float*)d_in[1];
    const float* s_c      = (const float*)d_in[2];
    const float* encOut   = (const float*)d_in[3];
    const float* encFeat  = (const float*)d_in[4];
    const float* mask     = (const float*)d_in[5];
    const float* c_t_1    = (const float*)d_in[6];
    const int*   ebev     = (const int*)  d_in[8];
    const float* coverage = (const float*)d_in[9];
    const int q = (n_in > 10 && in_sizes[10] <= 4) ? 11 : 10;
    const float* ri   = (const float*)d_in[q + 0];
    const float* embW = (const float*)d_in[q + 1];
    const float* WsW  = (const float*)d_in[q + 2];
    const float* Wsb  = (const float*)d_in[q + 3];
    const float* vW   = (const float*)d_in[q + 4];
    const float* WcW  = (const float*)d_in[q + 5];
    const float* WrW  = (const float*)d_in[q + 6];
    const float* xcW  = (const float*)d_in[q + 7];
    const float* xcb  = (const float*)d_in[q + 8];
    const float* Wih  = (const float*)d_in[q + 9];
    const float* Whh  = (const float*)d_in[q + 10];
    const float* bih  = (const float*)d_in[q + 11];
    const float* bhh  = (const float*)d_in[q + 12];
    const float* pgW  = (const float*)d_in[q + 13];
    const float* pgb  = (const float*)d_in[q + 14];
    const float* o1W  = (const float*)d_in[q + 15];
    const float* o1b  = (const float*)d_in[q + 16];
    const float* o2W  = (const float*)d_in[q + 17];
    const float* o2b  = (const float*)d_in[q + 18];
    float* out = (float*)d_out;
    const int aux = (out_size >= OUT_FULL()) ? 1 : 0;

    static int smem_set = 0;
    if (!smem_set) {
        cudaFuncSetAttribute(k_scores2, cudaFuncAttributeMaxDynamicSharedMemorySize, S2_SMEM);
        smem_set = 1;
    }

    k_cvt<<<256, 256>>>(WrW);
    k_prep<<<416, 256>>>(y, c_t_1, embW, s_h);
    k_xc<<<32, 256>>>(xcW, xcb);
    k_gates<<<512, 256>>>(Wih, Whh, bih, bhh);
    k_cell<<<128, 256>>>(s_c, out, aux);
    k_decfea<<<256, 256>>>(WsW, Wsb);
    k_scores2<<<200, 512, S2_SMEM>>>(ri, vW);
    k_scores<<<3200, 256>>>(encFeat, vW, WcW, coverage);
    k_softmax_t<<<64, 512>>>(mask, coverage, out, aux);
    k_ctx<<<dim3(4, 64), 256>>>(encOut, out, aux);
    k_pgen<<<8, 256>>>(pgW, pgb, out, aux);
    k_out1<<<128, 256>>>(o1W, o1b);
    k_logits<<<391, 256>>>(o2W, o2b);
    k_vsoftmax<<<64, 1024>>>(out);
    k_scatter<<<100, 256>>>(ebev, out);
}

// round 16
// speedup vs baseline: 1.4539x; 1.0192x over previous
#include <cuda_runtime.h>
#include <cuda_bf16.h>
#include <math.h>

#define BATCH 64
#define TKLEN 400
#define HID   512
#define H2    1024
#define VOCAB 50000
#define VEXT  50100

__host__ __device__ constexpr int OFF_H()    { return BATCH * VEXT; }
__host__ __device__ constexpr int OFF_C()    { return OFF_H()  + BATCH * HID; }
__host__ __device__ constexpr int OFF_CT()   { return OFF_C()  + BATCH * HID; }
__host__ __device__ constexpr int OFF_ATTN() { return OFF_CT() + BATCH * H2; }
__host__ __device__ constexpr int OFF_PG()   { return OFF_ATTN() + BATCH * TKLEN; }
__host__ __device__ constexpr int OFF_COV()  { return OFF_PG() + BATCH; }
__host__ __device__ constexpr int OUT_FULL() { return OFF_COV() + BATCH * TKLEN; }

// scratch (device globals) — all b-major
__device__ float g_xcat2 [64 * 1152];
__device__ float g_act2  [64 * 640];    // [x(128) ; h0(512)]
__device__ float g_gates [64 * 2048];
__device__ float g_c     [64 * 512];
__device__ float g_sthat2[64 * 1024];
__device__ float g_o1act2[64 * 1536];   // [h(512) ; c_struct(1024)]
__device__ float g_decfea[64 * 1024];
__device__ float g_scores [64 * 400];
__device__ float g_scores2[64 * 400];
__device__ float g_attn   [64 * 400];
__device__ float g_astruct[64 * 400];
__device__ float g_pgen[64];
__device__ __nv_bfloat16 g_out1bf[64 * 512];
__device__ __nv_bfloat16 g_wrbf[1024 * 512];
__device__ float g_logits[(size_t)64 * 50000];

__device__ __forceinline__ float tanhax(float x) {
    float y; asm("tanh.approx.f32 %0, %1;" : "=f"(y) : "f"(x)); return y;
}
__device__ __forceinline__ float sigm(float x) { return 1.f / (1.f + __expf(-x)); }

__device__ __forceinline__ void st8bf(__nv_bfloat16* p, float4 x, float4 y) {
    __nv_bfloat162* q = (__nv_bfloat162*)p;
    q[0] = __float22bfloat162_rn(make_float2(x.x, x.y));
    q[1] = __float22bfloat162_rn(make_float2(x.z, x.w));
    q[2] = __float22bfloat162_rn(make_float2(y.x, y.y));
    q[3] = __float22bfloat162_rn(make_float2(y.z, y.w));
}

// ---- convert WrW to bf16 ----
__global__ void k_cvt(const float* __restrict__ wr) {
    int i = blockIdx.x * 256 + threadIdx.x;
    const float* p = wr + (size_t)i * 8;
    st8bf(&g_wrbf[(size_t)i * 8], *(const float4*)p, *(const float4*)(p + 4));
}

// ---- prep: b-major concats + zero scores2 accumulator ----
__global__ void k_prep(const int* __restrict__ y, const float* __restrict__ c_t_1,
                       const float* __restrict__ embW, const float* __restrict__ s_h) {
    int i = blockIdx.x * 256 + threadIdx.x;
    const int N1 = 64 * 1152, N2 = N1 + 64 * 512, N3 = N2 + 64 * 400;
    if (i < N1) {
        int b = i / 1152, k = i - b * 1152;
        g_xcat2[i] = (k < 1024) ? c_t_1[b * 1024 + k]
                                : embW[(size_t)y[b] * 128 + (k - 1024)];
    } else if (i < N2) {
        int j = i - N1; int b = j >> 9, k = j & 511;
        g_act2[b * 640 + 128 + k] = s_h[b * 512 + k];
    } else if (i < N3) {
        g_scores2[i - N2] = 0.f;
    }
}

// ---- warp-split-K skinny GEMM: 4 j x 4 b per warp ----
__device__ __forceinline__ void skinny_acc(const float* __restrict__ W, int ldw,
                                           const float* __restrict__ A, int lda,
                                           int K, int j0, int b0, int lane, float* acc) {
    for (int k = lane; k < K; k += 32) {
        float wv0 = W[(size_t)(j0 + 0) * ldw + k];
        float wv1 = W[(size_t)(j0 + 1) * ldw + k];
        float wv2 = W[(size_t)(j0 + 2) * ldw + k];
        float wv3 = W[(size_t)(j0 + 3) * ldw + k];
        float av[4];
        #pragma unroll
        for (int bb = 0; bb < 4; bb++) av[bb] = A[(b0 + bb) * lda + k];
        #pragma unroll
        for (int bb = 0; bb < 4; bb++) {
            acc[0 * 4 + bb] = fmaf(wv0, av[bb], acc[0 * 4 + bb]);
            acc[1 * 4 + bb] = fmaf(wv1, av[bb], acc[1 * 4 + bb]);
            acc[2 * 4 + bb] = fmaf(wv2, av[bb], acc[2 * 4 + bb]);
            acc[3 * 4 + bb] = fmaf(wv3, av[bb], acc[3 * 4 + bb]);
        }
    }
}
__device__ __forceinline__ void skinny_red(float* acc) {
    #pragma unroll
    for (int i = 0; i < 16; i++) {
        float v = acc[i];
        v += __shfl_xor_sync(0xffffffffu, v, 16);
        v += __shfl_xor_sync(0xffffffffu, v, 8);
        v += __shfl_xor_sync(0xffffffffu, v, 4);
        v += __shfl_xor_sync(0xffffffffu, v, 2);
        v += __shfl_xor_sync(0xffffffffu, v, 1);
        acc[i] = v;
    }
}

// x = xc([c_t_1, y_emb]); J=128, K=1152 → 512 warps → 64 blocks
__global__ void k_xc(const float* __restrict__ xcW, const float* __restrict__ xcb) {
    int w = blockIdx.x * 8 + (threadIdx.x >> 5), lane = threadIdx.x & 31;
    int j0 = (w >> 4) * 4, b0 = (w & 15) * 4;
    float acc[16];
    #pragma unroll
    for (int i = 0; i < 16; i++) acc[i] = 0.f;
    skinny_acc(xcW, 1152, g_xcat2, 1152, 1152, j0, b0, lane, acc);
    skinny_red(acc);
    if (lane == 0) {
        #pragma unroll
        for (int jj = 0; jj < 4; jj++) {
            float bv = xcb[j0 + jj];
            #pragma unroll
            for (int bb = 0; bb < 4; bb++)
                g_act2[(b0 + bb) * 640 + j0 + jj] = bv + acc[jj * 4 + bb];
        }
    }
}

// gates; J=2048 → 8192 warps → 1024 blocks
__global__ void k_gates(const float* __restrict__ Wih, const float* __restrict__ Whh,
                        const float* __restrict__ bih, const float* __restrict__ bhh) {
    int w = blockIdx.x * 8 + (threadIdx.x >> 5), lane = threadIdx.x & 31;
    int j0 = (w >> 4) * 4, b0 = (w & 15) * 4;
    float acc[16];
    #pragma unroll
    for (int i = 0; i < 16; i++) acc[i] = 0.f;
    skinny_acc(Wih, 128, g_act2, 640, 128, j0, b0, lane, acc);
    skinny_acc(Whh, 512, g_act2 + 128, 640, 512, j0, b0, lane, acc);
    skinny_red(acc);
    if (lane == 0) {
        #pragma unroll
        for (int jj = 0; jj < 4; jj++) {
            float bv = bih[j0 + jj] + bhh[j0 + jj];
            #pragma unroll
            for (int bb = 0; bb < 4; bb++)
                g_gates[(b0 + bb) * 2048 + j0 + jj] = bv + acc[jj * 4 + bb];
        }
    }
}

__global__ void k_cell(const float* __restrict__ s_c, float* __restrict__ out, int aux) {
    int i = blockIdx.x * 256 + threadIdx.x;
    int b = i >> 9, u = i & 511;
    const float* gr = g_gates + b * 2048;
    float cn = sigm(gr[512 + u]) * s_c[b * 512 + u] + sigm(gr[u]) * tanhax(gr[1024 + u]);
    float hn = sigm(gr[1536 + u]) * tanhax(cn);
    g_c[b * 512 + u] = cn;
    g_sthat2[b * 1024 + u] = hn;  g_sthat2[b * 1024 + 512 + u] = cn;
    g_o1act2[b * 1536 + u] = hn;
    if (aux) { out[OFF_H() + i] = hn; out[OFF_C() + i] = cn; }
}

// dec_fea; J=1024 → 4096 warps → 512 blocks
__global__ void k_decfea(const float* __restrict__ WsW, const float* __restrict__ Wsb) {
    int w = blockIdx.x * 8 + (threadIdx.x >> 5), lane = threadIdx.x & 31;
    int j0 = (w >> 4) * 4, b0 = (w & 15) * 4;
    float acc[16];
    #pragma unroll
    for (int i = 0; i < 16; i++) acc[i] = 0.f;
    skinny_acc(WsW, 1024, g_sthat2, 1024, 1024, j0, b0, lane, acc);
    skinny_red(acc);
    if (lane == 0) {
        #pragma unroll
        for (int jj = 0; jj < 4; jj++) {
            float bv = Wsb[j0 + jj];
            #pragma unroll
            for (int bb = 0; bb < 4; bb++)
                g_decfea[(b0 + bb) * 1024 + j0 + jj] = bv + acc[jj * 4 + bb];
        }
    }
}

// ---- mma helpers ----
__device__ __forceinline__ void mma_bf16(float* c, unsigned a0, unsigned a1, unsigned a2,
                                         unsigned a3, unsigned b0, unsigned b1) {
    asm volatile(
        "mma.sync.aligned.m16n8k16.row.col.f32.bf16.bf16.f32 "
        "{%0,%1,%2,%3}, {%4,%5,%6,%7}, {%8,%9}, {%0,%1,%2,%3};\n"
        : "+f"(c[0]), "+f"(c[1]), "+f"(c[2]), "+f"(c[3])
        : "r"(a0), "r"(a1), "r"(a2), "r"(a3), "r"(b0), "r"(b1));
}
__device__ __forceinline__ void ldmA(unsigned& a0, unsigned& a1, unsigned& a2, unsigned& a3,
                                     unsigned addr) {
    asm volatile("ldmatrix.sync.aligned.m8n8.x4.shared.b16 {%0,%1,%2,%3}, [%4];"
                 : "=r"(a0), "=r"(a1), "=r"(a2), "=r"(a3) : "r"(addr));
}
__device__ __forceinline__ void ldmB(unsigned& b0, unsigned& b1, unsigned addr) {
    asm volatile("ldmatrix.sync.aligned.m8n8.x2.shared.b16 {%0,%1}, [%2];"
                 : "=r"(b0), "=r"(b1) : "r"(addr));
}

// ---- scores2: 64-row m-tiles, n-halves, 2 blocks/SM ----
#define S2_ABYT (64 * 520 * 2)          // 66560
#define S2_BROW 72
#define S2_BBUF (128 * S2_BROW)
#define S2_BBYT (2 * S2_BBUF * 2)       // 36864
#define S2_SMEM (S2_ABYT + S2_BBYT + 512)

__global__ __launch_bounds__(512, 2) void k_scores2(const float* __restrict__ ri,
                                                    const float* __restrict__ vW) {
    extern __shared__ char smraw[];
    __nv_bfloat16* As = (__nv_bfloat16*)smraw;                 // [64][520]
    __nv_bfloat16* Bs = (__nv_bfloat16*)(smraw + S2_ABYT);     // [2][128][72]
    float* s_sc = (float*)(smraw + S2_ABYT + S2_BBYT);         // [64]
    const int tid = threadIdx.x;
    const int m0 = blockIdx.y * 64;
    const int nh = blockIdx.x * 512;

    #pragma unroll
    for (int it = 0; it < 8; it++) {
        int idx = (tid + it * 512) * 8;
        int row = idx >> 9, col = idx & 511;
        const float* p = ri + (size_t)(m0 + row) * 512 + col;
        st8bf(&As[row * 520 + col], *(const float4*)p, *(const float4*)(p + 4));
    }
    if (tid < 64) s_sc[tid] = 0.f;
    __syncthreads();

    const int lane = tid & 31, wid = tid >> 5;
    const int wm = wid & 1, wn = wid >> 1;          // 2 x 32 rows, 8 x 16 cols
    const int g = lane >> 2, tg = lane & 3;

    unsigned As_u = (unsigned)__cvta_generic_to_shared(As);
    unsigned Bs_u = (unsigned)__cvta_generic_to_shared(Bs);
    int rowA = wm * 32 + (lane & 7) + ((lane >> 3) & 1) * 8;
    int colA = ((lane >> 4) & 1) * 8;
    unsigned aAddr0 = As_u + (rowA * 520 + colA) * 2;
    unsigned aAddr1 = aAddr0 + 16 * 520 * 2;
    unsigned bB[2];
    {
        int nR = lane & 7, tB = (lane >> 3) & 1;
        #pragma unroll
        for (int nt = 0; nt < 2; nt++)
            bB[nt] = Bs_u + ((wn * 16 + nt * 8 + nR) * S2_BROW + tB * 8) * 2;
    }
    const int r0 = tid >> 3, q0 = (tid & 7) * 8;    // rows r0 and r0+64

    float preg[2][2] = {{0.f, 0.f}, {0.f, 0.f}};
    int buf = 0;
    for (int nc = 0; nc < 4; nc++) {
        const int n0 = nh + nc * 128;
        const __nv_bfloat16* gB0 = g_wrbf + (size_t)(n0 + r0) * 512 + q0;
        const __nv_bfloat16* gB1 = gB0 + 64 * 512;
        float acc[2][2][4];
        #pragma unroll
        for (int a = 0; a < 2; a++)
            #pragma unroll
            for (int b = 0; b < 2; b++)
                #pragma unroll
                for (int c = 0; c < 4; c++) acc[a][b][c] = 0.f;

        uint4 v0 = *(const uint4*)gB0;
        uint4 v1 = *(const uint4*)gB1;
        __syncthreads();
        *(uint4*)&Bs[buf * S2_BBUF + r0 * S2_BROW + q0] = v0;
        *(uint4*)&Bs[buf * S2_BBUF + (r0 + 64) * S2_BROW + q0] = v1;
        __syncthreads();

        for (int kb = 0; kb < 8; kb++) {
            if (kb < 7) {
                v0 = *(const uint4*)(gB0 + (kb + 1) * 64);
                v1 = *(const uint4*)(gB1 + (kb + 1) * 64);
            }
            unsigned abyt = kb * 128;
            unsigned bbuf = buf * (S2_BBUF * 2);
            #pragma unroll
            for (int kk = 0; kk < 4; kk++) {
                unsigned a0[4], a1[4];
                ldmA(a0[0], a0[1], a0[2], a0[3], aAddr0 + abyt + kk * 32);
                ldmA(a1[0], a1[1], a1[2], a1[3], aAddr1 + abyt + kk * 32);
                #pragma unroll
                for (int nt = 0; nt < 2; nt++) {
                    unsigned b0, b1;
                    ldmB(b0, b1, bB[nt] + bbuf + kk * 32);
                    mma_bf16(acc[0][nt], a0[0], a0[1], a0[2], a0[3], b0, b1);
                    mma_bf16(acc[1][nt], a1[0], a1[1], a1[2], a1[3], b0, b1);
                }
            }
            if (kb < 7) {
                *(uint4*)&Bs[(buf ^ 1) * S2_BBUF + r0 * S2_BROW + q0] = v0;
                *(uint4*)&Bs[(buf ^ 1) * S2_BBUF + (r0 + 64) * S2_BROW + q0] = v1;
                __syncthreads();
                buf ^= 1;
            }
        }
        // fused tanh + v-dot epilogue (K fully accumulated for these 16 cols)
        #pragma unroll
        for (int mt = 0; mt < 2; mt++)
            #pragma unroll
            for (int half = 0; half < 2; half++) {
                int mg = m0 + wm * 32 + mt * 16 + g + half * 8;
                const float* df = g_decfea + (mg / TKLEN) * 1024;
                float p = 0.f;
                #pragma unroll
                for (int nt = 0; nt < 2; nt++) {
                    int nn = n0 + wn * 16 + nt * 8 + 2 * tg;
                    p += vW[nn]     * tanhax(acc[mt][nt][half * 2]     + df[nn]);
                    p += vW[nn + 1] * tanhax(acc[mt][nt][half * 2 + 1] + df[nn + 1]);
                }
                preg[mt][half] += p;
            }
    }
    #pragma unroll
    for (int mt = 0; mt < 2; mt++)
        #pragma unroll
        for (int half = 0; half < 2; half++) {
            float p = preg[mt][half];
            p += __shfl_xor_sync(0xffffffffu, p, 1);
            p += __shfl_xor_sync(0xffffffffu, p, 2);
            if (tg == 0) atomicAdd(&s_sc[wm * 32 + mt * 16 + g + half * 8], p);
        }
    __syncthreads();
    if (tid < 64) atomicAdd(&g_scores2[m0 + tid], s_sc[tid]);
}

// ---- scores: v . tanh(encFeat + dec_fea + cov*Wc), warp per (b,t) ----
__global__ void k_scores(const float* __restrict__ encFeat, const float* __restrict__ vW,
                         const float* __restrict__ WcW, const float* __restrict__ coverage) {
    int w = blockIdx.x * 8 + (threadIdx.x >> 5);
    int lane = threadIdx.x & 31, b = w / TKLEN;
    const float4* ef = (const float4*)(encFeat + (size_t)w * 1024);
    const float4* df = (const float4*)(g_decfea + b * 1024);
    const float4* v4 = (const float4*)vW;
    const float4* w4 = (const float4*)WcW;
    float cov = coverage[w], acc = 0.f;
    #pragma unroll
    for (int i = 0; i < 8; i++) {
        int id = lane + i * 32;
        float4 e = ef[id], d = df[id], vv = v4[id], wc = w4[id];
        acc += vv.x * tanhax(e.x + d.x + cov * wc.x);
        acc += vv.y * tanhax(e.y + d.y + cov * wc.y);
        acc += vv.z * tanhax(e.z + d.z + cov * wc.z);
        acc += vv.w * tanhax(e.w + d.w + cov * wc.w);
    }
    for (int o = 16; o > 0; o >>= 1) acc += __shfl_xor_sync(0xffffffffu, acc, o);
    if (lane == 0) g_scores[w] = acc;
}

// ---- both t-softmaxes ----
__global__ void k_softmax_t(const float* __restrict__ mask, const float* __restrict__ coverage,
                            float* __restrict__ out, int aux) {
    int b = blockIdx.x, t = threadIdx.x;
    __shared__ float sm[512];
    float s = (t < TKLEN) ? g_scores[b * TKLEN + t] : -1e30f;
    sm[t] = s; __syncthreads();
    for (int st = 256; st > 0; st >>= 1) { if (t < st) sm[t] = fmaxf(sm[t], sm[t + st]); __syncthreads(); }
    float mx = sm[0]; __syncthreads();
    float e = (t < TKLEN) ? __expf(s - mx) : 0.f;
    sm[t] = e; __syncthreads();
    for (int st = 256; st > 0; st >>= 1) { if (t < st) sm[t] += sm[t + st]; __syncthreads(); }
    float S = sm[0]; __syncthreads();
    float a = (t < TKLEN) ? (e / S) * mask[b * TKLEN + t] : 0.f;
    sm[t] = a; __syncthreads();
    for (int st = 256; st > 0; st >>= 1) { if (t < st) sm[t] += sm[t + st]; __syncthreads(); }
    float Sm = sm[0]; __syncthreads();
    if (t < TKLEN) {
        float attn = a / Sm;
        g_attn[b * TKLEN + t] = attn;
        if (aux) {
            out[OFF_ATTN() + b * TKLEN + t] = attn;
            out[OFF_COV()  + b * TKLEN + t] = coverage[b * TKLEN + t] + attn;
        }
    }
    __syncthreads();
    float s2 = (t < TKLEN) ? g_scores2[b * TKLEN + t] : -1e30f;
    sm[t] = s2; __syncthreads();
    for (int st = 256; st > 0; st >>= 1) { if (t < st) sm[t] = fmaxf(sm[t], sm[t + st]); __syncthreads(); }
    float mx2 = sm[0]; __syncthreads();
    float e2 = (t < TKLEN) ? __expf(s2 - mx2) : 0.f;
    sm[t] = e2; __syncthreads();
    for (int st = 256; st > 0; st >>= 1) { if (t < st) sm[t] += sm[t + st]; __syncthreads(); }
    float S2 = sm[0];
    if (t < TKLEN) g_astruct[b * TKLEN + t] = (e2 / S2) * mask[b * TKLEN + t];
}

// ---- c_t & c_struct in one pass ----
__global__ void k_ctx(const float* __restrict__ encOut, float* __restrict__ out, int aux) {
    int b = blockIdx.y, n = blockIdx.x * 256 + threadIdx.x;
    __shared__ float sa[400], sb2[400];
    for (int t = threadIdx.x; t < 400; t += 256) {
        sa[t]  = g_attn[b * TKLEN + t];
        sb2[t] = g_astruct[b * TKLEN + t];
    }
    __syncthreads();
    const float* E = encOut + (size_t)b * TKLEN * 1024 + n;
    float a1 = 0.f, a2 = 0.f;
    #pragma unroll 4
    for (int t = 0; t < 400; t++) {
        float e = E[(size_t)t * 1024];
        a1 = fmaf(sa[t], e, a1);
        a2 = fmaf(sb2[t], e, a2);
    }
    g_o1act2[b * 1536 + 512 + n] = a2;
    if (aux) out[OFF_CT() + b * 1024 + n] = a1;
}

__global__ void k_pgen(const float* __restrict__ pgW, const float* __restrict__ pgb,
                       float* __restrict__ out, int aux) {
    int b = blockIdx.x * 8 + (threadIdx.x >> 5), lane = threadIdx.x & 31;
    float acc = 0.f;
    for (int k = lane; k < 2176; k += 32) {
        float xv;
        if (k < 1024)      xv = g_o1act2[b * 1536 + 512 + k];
        else if (k < 1536) xv = g_o1act2[b * 1536 + (k - 1024)];
        else if (k < 2048) xv = g_c[b * 512 + k - 1536];
        else               xv = g_act2[b * 640 + (k - 2048)];
        acc = fmaf(pgW[k], xv, acc);
    }
    for (int o = 16; o > 0; o >>= 1) acc += __shfl_xor_sync(0xffffffffu, acc, o);
    if (lane == 0) {
        float p = sigm(acc + pgb[0]);
        g_pgen[b] = p;
        if (aux) out[OFF_PG() + b] = p;
    }
}

// out1; J=512 → 2048 warps → 256 blocks
__global__ void k_out1(const float* __restrict__ o1W, const float* __restrict__ o1b) {
    int w = blockIdx.x * 8 + (threadIdx.x >> 5), lane = threadIdx.x & 31;
    int j0 = (w >> 4) * 4, b0 = (w & 15) * 4;
    float acc[16];
    #pragma unroll
    for (int i = 0; i < 16; i++) acc[i] = 0.f;
    skinny_acc(o1W, 1536, g_o1act2, 1536, 1536, j0, b0, lane, acc);
    skinny_red(acc);
    if (lane == 0) {
        #pragma unroll
        for (int jj = 0; jj < 4; jj++) {
            float bv = o1b[j0 + jj];
            #pragma unroll
            for (int bb = 0; bb < 4; bb++)
                g_out1bf[(b0 + bb) * 512 + j0 + jj] = __float2bfloat16(bv + acc[jj * 4 + bb]);
        }
    }
}

// ---- logits (64 x 50000) bf16 MMA; tile 64m x 128n, K=512 ----
__global__ __launch_bounds__(256) void k_logits(const float* __restrict__ o2W,
                                                const float* __restrict__ o2b) {
    __shared__ __nv_bfloat16 As[2][64][24];
    __shared__ __nv_bfloat16 Bs[2][128][24];
    const int tid = threadIdx.x, n0 = blockIdx.x * 128;
    const int rA = tid >> 2, cA = (tid & 3) * 4;
    const __nv_bfloat16* aG = g_out1bf + rA * 512 + cA;
    const int rB = tid >> 1, cbB = (tid & 1) * 8, ngB = n0 + rB;
    const bool bok = (ngB < VOCAB);
    const float* bG = o2W + (size_t)ngB * 512 + cbB;

    __nv_bfloat162 pa0 = *(const __nv_bfloat162*)aG;
    __nv_bfloat162 pa1 = *(const __nv_bfloat162*)(aG + 2);
    float4 fb0 = make_float4(0, 0, 0, 0), fb1 = fb0;
    if (bok) { fb0 = *(const float4*)bG; fb1 = *(const float4*)(bG + 4); }
    *(__nv_bfloat162*)&As[0][rA][cA]     = pa0;
    *(__nv_bfloat162*)&As[0][rA][cA + 2] = pa1;
    st8bf(&Bs[0][rB][cbB], fb0, fb1);
    __syncthreads();

    const int lane = tid & 31, wid = tid >> 5;
    const int wm = wid & 1, wn = wid >> 1, g = lane >> 2, tg = lane & 3;
    float acc[2][4][4] = {};

    int buf = 0;
    for (int ks = 0; ks < 32; ks++) {
        if (ks < 31) {
            const __nv_bfloat16* ap = aG + (ks + 1) * 16;
            pa0 = *(const __nv_bfloat162*)ap; pa1 = *(const __nv_bfloat162*)(ap + 2);
            if (bok) {
                const float* bp = bG + (ks + 1) * 16;
                fb0 = *(const float4*)bp; fb1 = *(const float4*)(bp + 4);
            }
        }
        unsigned afr[2][4];
        #pragma unroll
        for (int mt = 0; mt < 2; mt++) {
            int rb = wm * 32 + mt * 16;
            afr[mt][0] = *(const unsigned*)&As[buf][rb + g][2 * tg];
            afr[mt][1] = *(const unsigned*)&As[buf][rb + g + 8][2 * tg];
            afr[mt][2] = *(const unsigned*)&As[buf][rb + g][2 * tg + 8];
            afr[mt][3] = *(const unsigned*)&As[buf][rb + g + 8][2 * tg + 8];
        }
        #pragma unroll
        for (int nt = 0; nt < 4; nt++) {
            int nr = wn * 32 + nt * 8 + g;
            unsigned b0 = *(const unsigned*)&Bs[buf][nr][2 * tg];
            unsigned b1 = *(const unsigned*)&Bs[buf][nr][2 * tg + 8];
            mma_bf16(acc[0][nt], afr[0][0], afr[0][1], afr[0][2], afr[0][3], b0, b1);
            mma_bf16(acc[1][nt], afr[1][0], afr[1][1], afr[1][2], afr[1][3], b0, b1);
        }
        if (ks < 31) {
            *(__nv_bfloat162*)&As[buf ^ 1][rA][cA]     = pa0;
            *(__nv_bfloat162*)&As[buf ^ 1][rA][cA + 2] = pa1;
            st8bf(&Bs[buf ^ 1][rB][cbB], fb0, fb1);
            __syncthreads();
            buf ^= 1;
        }
    }
    #pragma unroll
    for (int mt = 0; mt < 2; mt++)
        #pragma unroll
        for (int nt = 0; nt < 4; nt++) {
            int nn = n0 + wn * 32 + nt * 8 + 2 * tg;
            if (nn < VOCAB) {
                int mg = wm * 32 + mt * 16 + g;
                float bb0 = o2b[nn], bb1 = o2b[nn + 1];
                g_logits[(size_t)mg * VOCAB + nn]           = acc[mt][nt][0] + bb0;
                g_logits[(size_t)mg * VOCAB + nn + 1]       = acc[mt][nt][1] + bb1;
                g_logits[(size_t)(mg + 8) * VOCAB + nn]     = acc[mt][nt][2] + bb0;
                g_logits[(size_t)(mg + 8) * VOCAB + nn + 1] = acc[mt][nt][3] + bb1;
            }
        }
}

// ---- vocab softmax * p_gen + zeroed OOV ----
__global__ void k_vsoftmax(float* __restrict__ out) {
    int b = blockIdx.x, t = threadIdx.x;
    __shared__ float sm[1024];
    const float* L = g_logits + (size_t)b * VOCAB;
    float mx = -1e30f;
    for (int n = t; n < VOCAB; n += 1024) mx = fmaxf(mx, L[n]);
    sm[t] = mx; __syncthreads();
    for (int s = 512; s > 0; s >>= 1) { if (t < s) sm[t] = fmaxf(sm[t], sm[t + s]); __syncthreads(); }
    mx = sm[0]; __syncthreads();
    float sum = 0.f;
    for (int n = t; n < VOCAB; n += 1024) sum += __expf(L[n] - mx);
    sm[t] = sum; __syncthreads();
    for (int s = 512; s > 0; s >>= 1) { if (t < s) sm[t] += sm[t + s]; __syncthreads(); }
    float scale = g_pgen[b] / sm[0];
    float* O = out + (size_t)b * VEXT;
    for (int n = t; n < VEXT; n += 1024)
        O[n] = (n < VOCAB) ? scale * __expf(L[n] - mx) : 0.f;
}

__global__ void k_scatter(const int* __restrict__ ebev, float* __restrict__ out) {
    int i = blockIdx.x * 256 + threadIdx.x;
    if (i >= BATCH * TKLEN) return;
    int b = i / TKLEN;
    atomicAdd(&out[(size_t)b * VEXT + ebev[i]], (1.f - g_pgen[b]) * g_attn[i]);
}

extern "C" void kernel_launch(void* const* d_in, const int* in_sizes, int n_in,
                              void* d_out, int out_size) {
    const int*   y        = (const int*)  d_in[0];
    const float* s_h      = (const float*)d_in[1];
    const float* s_c      = (const float*)d_in[2];
    const float* encOut   = (const float*)d_in[3];
    const float* encFeat  = (const float*)d_in[4];
    const float* mask     = (const float*)d_in[5];
    const float* c_t_1    = (const float*)d_in[6];
    const int*   ebev     = (const int*)  d_in[8];
    const float* coverage = (const float*)d_in[9];
    const int q = (n_in > 10 && in_sizes[10] <= 4) ? 11 : 10;
    const float* ri   = (const float*)d_in[q + 0];
    const float* embW = (const float*)d_in[q + 1];
    const float* WsW  = (const float*)d_in[q + 2];
    const float* Wsb  = (const float*)d_in[q + 3];
    const float* vW   = (const float*)d_in[q + 4];
    const float* WcW  = (const float*)d_in[q + 5];
    const float* WrW  = (const float*)d_in[q + 6];
    const float* xcW  = (const float*)d_in[q + 7];
    const float* xcb  = (const float*)d_in[q + 8];
    const float* Wih  = (const float*)d_in[q + 9];
    const float* Whh  = (const float*)d_in[q + 10];
    const float* bih  = (const float*)d_in[q + 11];
    const float* bhh  = (const float*)d_in[q + 12];
    const float* pgW  = (const float*)d_in[q + 13];
    const float* pgb  = (const float*)d_in[q + 14];
    const float* o1W  = (const float*)d_in[q + 15];
    const float* o1b  = (const float*)d_in[q + 16];
    const float* o2W  = (const float*)d_in[q + 17];
    const float* o2b  = (const float*)d_in[q + 18];
    float* out = (float*)d_out;
    const int aux = (out_size >= OUT_FULL()) ? 1 : 0;

    static int smem_set = 0;
    if (!smem_set) {
        cudaFuncSetAttribute(k_scores2, cudaFuncAttributeMaxDynamicSharedMemorySize, S2_SMEM);
        smem_set = 1;
    }

    k_cvt<<<256, 256>>>(WrW);
    k_prep<<<516, 256>>>(y, c_t_1, embW, s_h);
    k_xc<<<64, 256>>>(xcW, xcb);
    k_gates<<<1024, 256>>>(Wih, Whh, bih, bhh);
    k_cell<<<128, 256>>>(s_c, out, aux);
    k_decfea<<<512, 256>>>(WsW, Wsb);
    k_scores2<<<dim3(2, 400), 512, S2_SMEM>>>(ri, vW);
    k_scores<<<3200, 256>>>(encFeat, vW, WcW, coverage);
    k_softmax_t<<<64, 512>>>(mask, coverage, out, aux);
    k_ctx<<<dim3(4, 64), 256>>>(encOut, out, aux);
    k_pgen<<<8, 256>>>(pgW, pgb, out, aux);
    k_out1<<<256, 256>>>(o1W, o1b);
    k_logits<<<391, 256>>>(o2W, o2b);
    k_vsoftmax<<<64, 1024>>>(out);
    k_scatter<<<100, 256>>>(ebev, out);
}